// round 13
// baseline (speedup 1.0000x reference)
#include <cuda_runtime.h>
#include <cstdint>

#define FEAT_DIM  8
#define TABLE     1048577
#define LAST_ROW  (TABLE - 1)

// Proven gather layout: 2 lanes/point, one __ldcg LDG.128 half-row per corner.
// New: persistent grid-stride blocks (one wave), and levels 1+2 merged into
// a single kernel (their two tables = 67MB still fit L2), eliminating one
// out-RMW round, one coord read, and one launch tail.

__device__ __forceinline__ void level_weights(float x, float y, float z,
                                              float s, float* w)
{
    float cx = fmaf(s, x, s), cy = fmaf(s, y, s), cz = fmaf(s, z, s);
    float dx = cx - floorf(cx), dy = cy - floorf(cy), dz = cz - floorf(cz);
    dx = dx * dx * fmaf(-2.f, dx, 3.f);   // smoothstep 3d^2-2d^3
    dy = dy * dy * fmaf(-2.f, dy, 3.f);
    dz = dz * dz * fmaf(-2.f, dz, 3.f);
    const float ex = 1.f - dx, ey = 1.f - dy, ez = 1.f - dz;
    const float exey = ex * ey, exdy = ex * dy;
    const float dxey = dx * ey, dxdy = dx * dy;
    w[0] = exey * ez; w[1] = exey * dz;
    w[2] = exdy * ez; w[3] = exdy * dz;
    w[4] = dxey * ez; w[5] = dxey * dz;
    w[6] = dxdy * ez; w[7] = dxdy * dz;
}

__device__ __forceinline__ void gather_level(const char* fb8,   // feat + half*16
                                             const int* __restrict__ idx,
                                             size_t p, const float* w,
                                             float& a0, float& a1,
                                             float& a2, float& a3)
{
    const int4* ip = reinterpret_cast<const int4*>(idx + p * 8);
    const int4 ia = __ldcs(ip);
    const int4 ib = __ldcs(ip + 1);
    const int id[8] = {ia.x, ia.y, ia.z, ia.w, ib.x, ib.y, ib.z, ib.w};
    #pragma unroll
    for (int c = 0; c < 8; c++) {
        float wc = (id[c] == LAST_ROW) ? 0.f : w[c];  // features[:,-1,:]=0
        const float4 g = __ldcg(reinterpret_cast<const float4*>(
            fb8 + (size_t)(unsigned)id[c] * 32u));
        a0 = fmaf(wc, g.x, a0);
        a1 = fmaf(wc, g.y, a1);
        a2 = fmaf(wc, g.z, a2);
        a3 = fmaf(wc, g.w, a3);
    }
}

// Kernel A: level i=0 (table 2, s=2048). Pure write of out.
__global__ __launch_bounds__(256) void octree_pass0_kernel(
    const float* __restrict__ coord,
    const float* __restrict__ feat,    // features + 2*TABLE*8
    const int*   __restrict__ idx,     // indices + 0
    float*       __restrict__ out,
    int n)
{
    const int lane  = threadIdx.x & 31;
    const int half  = lane & 1;
    const int sub   = lane >> 1;                 // 0..15
    const int gwarp = (blockIdx.x * blockDim.x + threadIdx.x) >> 5;
    const int wtot  = (gridDim.x * blockDim.x) >> 5;

    for (int base = gwarp * 16; base < n; base += wtot * 16) {
        const int p0 = base + sub;
        const bool valid = (p0 < n);
        const int p = valid ? p0 : (n - 1);

        const float x = __ldcs(&coord[3 * (size_t)p + 0]);
        const float y = __ldcs(&coord[3 * (size_t)p + 1]);
        const float z = __ldcs(&coord[3 * (size_t)p + 2]);
        float w[8];
        level_weights(x, y, z, 2048.f, w);

        float a0 = 0.f, a1 = 0.f, a2 = 0.f, a3 = 0.f;
        gather_level((const char*)feat + half * 16, idx, (size_t)p, w,
                     a0, a1, a2, a3);

        if (valid) {
            float4* op = reinterpret_cast<float4*>(
                out + (size_t)p * 8 + half * 4);
            *op = make_float4(a0, a1, a2, a3);
        }
    }
}

// Kernel B: levels i=1 (table 1, s=1024) and i=2 (table 0, s=512), fused.
// Both tables (67MB) stay L2-resident. RMW of out.
__global__ __launch_bounds__(256) void octree_pass12_kernel(
    const float* __restrict__ coord,
    const float* __restrict__ features,  // base
    const int*   __restrict__ indices,   // base
    float*       __restrict__ out,
    int n)
{
    const int lane  = threadIdx.x & 31;
    const int half  = lane & 1;
    const int sub   = lane >> 1;
    const int gwarp = (blockIdx.x * blockDim.x + threadIdx.x) >> 5;
    const int wtot  = (gridDim.x * blockDim.x) >> 5;

    const float* feat1 = features + (size_t)1 * TABLE * FEAT_DIM;
    const float* feat0 = features;
    const int*   idx1  = indices + (size_t)1 * n * 8;
    const int*   idx2  = indices + (size_t)2 * n * 8;

    for (int base = gwarp * 16; base < n; base += wtot * 16) {
        const int p0 = base + sub;
        const bool valid = (p0 < n);
        const int p = valid ? p0 : (n - 1);

        const float x = __ldcs(&coord[3 * (size_t)p + 0]);
        const float y = __ldcs(&coord[3 * (size_t)p + 1]);
        const float z = __ldcs(&coord[3 * (size_t)p + 2]);

        const float4 prev = __ldcs(reinterpret_cast<const float4*>(
            out + (size_t)p * 8 + half * 4));
        float a0 = prev.x, a1 = prev.y, a2 = prev.z, a3 = prev.w;

        float w[8];
        level_weights(x, y, z, 1024.f, w);
        gather_level((const char*)feat1 + half * 16, idx1, (size_t)p, w,
                     a0, a1, a2, a3);

        level_weights(x, y, z, 512.f, w);
        gather_level((const char*)feat0 + half * 16, idx2, (size_t)p, w,
                     a0, a1, a2, a3);

        if (valid) {
            float4* op = reinterpret_cast<float4*>(
                out + (size_t)p * 8 + half * 4);
            *op = make_float4(a0, a1, a2, a3);
        }
    }
}

extern "C" void kernel_launch(void* const* d_in, const int* in_sizes, int n_in,
                              void* d_out, int out_size)
{
    const float* coord    = (const float*)d_in[0];  // (N,3)
    const float* features = (const float*)d_in[1];  // (3,TABLE,8)
    const int*   indices  = (const int*)d_in[2];    // (3,N,8)
    float*       out      = (float*)d_out;          // (N,8)

    const int n = in_sizes[0] / 3;
    const int threads = 256;
    const int blocks = 148 * 8;   // one resident wave of persistent blocks

    octree_pass0_kernel<<<blocks, threads>>>(
        coord, features + (size_t)2 * TABLE * FEAT_DIM,
        indices, out, n);
    octree_pass12_kernel<<<blocks, threads>>>(
        coord, features, indices, out, n);
}

// round 14
// speedup vs baseline: 1.0704x; 1.0704x over previous
#include <cuda_runtime.h>
#include <cstdint>

#define FEAT_DIM  8
#define TABLE     1048577
#define LAST_ROW  (TABLE - 1)

// R12 structure (3 passes, one 33.5MB table per pass -> L2-resident gathers;
// 2 lanes/point, one __ldcg LDG.128 half-row per corner) + persistent
// single-wave grid. __launch_bounds__(256,8) pins 8 blocks/SM (<=32 regs) so
// persistence does not cost occupancy; one wave removes ~9us/pass of wave
// transitions.
template <bool FIRST>
__global__ __launch_bounds__(256, 8) void octree_level_kernel(
    const float* __restrict__ coord,   // (N,3)
    const float* __restrict__ feat,    // (TABLE,8) for this level
    const int*   __restrict__ idx,     // (N,8) for this level
    float*       __restrict__ out,     // (N,8)
    int n, float s)                    // s = 2^(level-1)
{
    const int lane  = threadIdx.x & 31;
    const int half  = lane & 1;                 // which 16B half of the row
    const int sub   = lane >> 1;                // 0..15
    const int gwarp = (blockIdx.x * blockDim.x + threadIdx.x) >> 5;
    const int wtot  = (gridDim.x * blockDim.x) >> 5;
    const char* fb  = (const char*)feat + half * 16;   // my 16B half

    for (int base = gwarp * 16; base < n; base += wtot * 16) {
        const int p0 = base + sub;
        const bool valid = (p0 < n);
        const int p = valid ? p0 : (n - 1);

        const float x = __ldcs(&coord[3 * (size_t)p + 0]);
        const float y = __ldcs(&coord[3 * (size_t)p + 1]);
        const float z = __ldcs(&coord[3 * (size_t)p + 2]);
        float cx = fmaf(s, x, s), cy = fmaf(s, y, s), cz = fmaf(s, z, s);
        float dx = cx - floorf(cx), dy = cy - floorf(cy), dz = cz - floorf(cz);
        dx = dx * dx * fmaf(-2.f, dx, 3.f);   // smoothstep 3d^2-2d^3
        dy = dy * dy * fmaf(-2.f, dy, 3.f);
        dz = dz * dz * fmaf(-2.f, dz, 3.f);

        const float ex = 1.f - dx, ey = 1.f - dy, ez = 1.f - dz;
        const float exey = ex * ey, exdy = ex * dy;
        const float dxey = dx * ey, dxdy = dx * dy;
        float w[8];
        w[0] = exey * ez; w[1] = exey * dz;
        w[2] = exdy * ez; w[3] = exdy * dz;
        w[4] = dxey * ez; w[5] = dxey * dz;
        w[6] = dxdy * ez; w[7] = dxdy * dz;

        // this point's 8 indices (lane pairs read same 32B: L1 broadcast)
        const int4* ip = reinterpret_cast<const int4*>(idx + (size_t)p * 8);
        const int4 ia = __ldcs(ip);
        const int4 ib = __ldcs(ip + 1);
        const int id[8] = {ia.x, ia.y, ia.z, ia.w, ib.x, ib.y, ib.z, ib.w};

        float a0, a1, a2, a3;
        if (FIRST) { a0 = a1 = a2 = a3 = 0.f; }
        else {
            const float4 prev = __ldcs(reinterpret_cast<const float4*>(
                out + (size_t)p * 8 + half * 4));
            a0 = prev.x; a1 = prev.y; a2 = prev.z; a3 = prev.w;
        }

        #pragma unroll
        for (int c = 0; c < 8; c++) {
            float wc = (id[c] == LAST_ROW) ? 0.f : w[c];  // features[:,-1,:]=0
            const float4 g = __ldcg(reinterpret_cast<const float4*>(
                fb + (size_t)(unsigned)id[c] * 32u));     // L2-only gather
            a0 = fmaf(wc, g.x, a0);
            a1 = fmaf(wc, g.y, a1);
            a2 = fmaf(wc, g.z, a2);
            a3 = fmaf(wc, g.w, a3);
        }

        if (valid) {
            float4* op = reinterpret_cast<float4*>(
                out + (size_t)p * 8 + half * 4);
            *op = make_float4(a0, a1, a2, a3);
        }
    }
}

extern "C" void kernel_launch(void* const* d_in, const int* in_sizes, int n_in,
                              void* d_out, int out_size)
{
    const float* coord    = (const float*)d_in[0];  // (N,3)
    const float* features = (const float*)d_in[1];  // (3,TABLE,8)
    const int*   indices  = (const int*)d_in[2];    // (3,N,8)
    float*       out      = (float*)d_out;          // (N,8)

    const int n = in_sizes[0] / 3;
    const int threads = 256;
    const int blocks = 148 * 8;   // exactly one resident wave @ 8 blocks/SM

    // pass i: indices[i] pairs with features[2-i], level = 12-i, s = 2^(level-1)
    octree_level_kernel<true><<<blocks, threads>>>(
        coord, features + (size_t)2 * TABLE * FEAT_DIM,
        indices + (size_t)0 * n * 8, out, n, 2048.f);
    octree_level_kernel<false><<<blocks, threads>>>(
        coord, features + (size_t)1 * TABLE * FEAT_DIM,
        indices + (size_t)1 * n * 8, out, n, 1024.f);
    octree_level_kernel<false><<<blocks, threads>>>(
        coord, features + (size_t)0 * TABLE * FEAT_DIM,
        indices + (size_t)2 * n * 8, out, n, 512.f);
}

// round 16
// speedup vs baseline: 1.1907x; 1.1123x over previous
#include <cuda_runtime.h>
#include <cstdint>

#define FEAT_DIM  8
#define TABLE     1048577
#define LAST_ROW  (TABLE - 1)

// Proven gather layout (R12): 2 lanes/point, one __ldcg LDG.128 half-row per
// corner, small-block grid (NOT persistent - disproven in R13/R14).
// New vs R12: passes 2+3 merged into one kernel with sequential level
// processing and occupancy pinned to 8 blocks/SM, removing one full
// out-read round (32MB + wavefronts), one coord read, and one launch gap.

__device__ __forceinline__ void level_weights(float x, float y, float z,
                                              float s, float* w)
{
    float cx = fmaf(s, x, s), cy = fmaf(s, y, s), cz = fmaf(s, z, s);
    float dx = cx - floorf(cx), dy = cy - floorf(cy), dz = cz - floorf(cz);
    dx = dx * dx * fmaf(-2.f, dx, 3.f);   // smoothstep 3d^2-2d^3
    dy = dy * dy * fmaf(-2.f, dy, 3.f);
    dz = dz * dz * fmaf(-2.f, dz, 3.f);
    const float ex = 1.f - dx, ey = 1.f - dy, ez = 1.f - dz;
    const float exey = ex * ey, exdy = ex * dy;
    const float dxey = dx * ey, dxdy = dx * dy;
    w[0] = exey * ez; w[1] = exey * dz;
    w[2] = exdy * ez; w[3] = exdy * dz;
    w[4] = dxey * ez; w[5] = dxey * dz;
    w[6] = dxdy * ez; w[7] = dxdy * dz;
}

__device__ __forceinline__ void gather_level(const char* fb8,   // feat + half*16
                                             const int* __restrict__ idx,
                                             size_t p, const float* w,
                                             float& a0, float& a1,
                                             float& a2, float& a3)
{
    const int4* ip = reinterpret_cast<const int4*>(idx + p * 8);
    const int4 ia = __ldcs(ip);
    const int4 ib = __ldcs(ip + 1);
    const int id[8] = {ia.x, ia.y, ia.z, ia.w, ib.x, ib.y, ib.z, ib.w};
    #pragma unroll
    for (int c = 0; c < 8; c++) {
        float wc = (id[c] == LAST_ROW) ? 0.f : w[c];  // features[:,-1,:]=0
        const float4 g = __ldcg(reinterpret_cast<const float4*>(
            fb8 + (size_t)(unsigned)id[c] * 32u));    // L2-only gather
        a0 = fmaf(wc, g.x, a0);
        a1 = fmaf(wc, g.y, a1);
        a2 = fmaf(wc, g.z, a2);
        a3 = fmaf(wc, g.w, a3);
    }
}

// Kernel A: level i=0 (table 2, s=2048). Pure write of out. Exact R12 shape.
__global__ __launch_bounds__(256, 8) void octree_pass0_kernel(
    const float* __restrict__ coord,
    const float* __restrict__ feat,    // features + 2*TABLE*8
    const int*   __restrict__ idx,     // indices + 0
    float*       __restrict__ out,
    int n)
{
    const int lane  = threadIdx.x & 31;
    const int half  = lane & 1;
    const int gwarp = (blockIdx.x * blockDim.x + threadIdx.x) >> 5;
    const int p0    = gwarp * 16 + (lane >> 1);
    const bool valid = (p0 < n);
    const int p = valid ? p0 : (n > 0 ? n - 1 : 0);

    const float x = __ldcs(&coord[3 * (size_t)p + 0]);
    const float y = __ldcs(&coord[3 * (size_t)p + 1]);
    const float z = __ldcs(&coord[3 * (size_t)p + 2]);
    float w[8];
    level_weights(x, y, z, 2048.f, w);

    float a0 = 0.f, a1 = 0.f, a2 = 0.f, a3 = 0.f;
    gather_level((const char*)feat + half * 16, idx, (size_t)p, w,
                 a0, a1, a2, a3);

    if (valid) {
        float4* op = reinterpret_cast<float4*>(out + (size_t)p * 8 + half * 4);
        *op = make_float4(a0, a1, a2, a3);
    }
}

// Kernel B: levels i=1 (table 1, s=1024) then i=2 (table 0, s=512),
// processed sequentially to keep live registers low. RMW of out.
__global__ __launch_bounds__(256, 8) void octree_pass12_kernel(
    const float* __restrict__ coord,
    const float* __restrict__ features,  // base
    const int*   __restrict__ indices,   // base
    float*       __restrict__ out,
    int n)
{
    const int lane  = threadIdx.x & 31;
    const int half  = lane & 1;
    const int gwarp = (blockIdx.x * blockDim.x + threadIdx.x) >> 5;
    const int p0    = gwarp * 16 + (lane >> 1);
    const bool valid = (p0 < n);
    const int p = valid ? p0 : (n > 0 ? n - 1 : 0);

    const float x = __ldcs(&coord[3 * (size_t)p + 0]);
    const float y = __ldcs(&coord[3 * (size_t)p + 1]);
    const float z = __ldcs(&coord[3 * (size_t)p + 2]);

    const float4 prev = __ldcs(reinterpret_cast<const float4*>(
        out + (size_t)p * 8 + half * 4));
    float a0 = prev.x, a1 = prev.y, a2 = prev.z, a3 = prev.w;

    {   // level i=1: table 1, s=1024
        float w[8];
        level_weights(x, y, z, 1024.f, w);
        gather_level((const char*)(features + (size_t)1 * TABLE * FEAT_DIM)
                         + half * 16,
                     indices + (size_t)1 * n * 8, (size_t)p, w,
                     a0, a1, a2, a3);
    }
    {   // level i=2: table 0, s=512
        float w[8];
        level_weights(x, y, z, 512.f, w);
        gather_level((const char*)features + half * 16,
                     indices + (size_t)2 * n * 8, (size_t)p, w,
                     a0, a1, a2, a3);
    }

    if (valid) {
        float4* op = reinterpret_cast<float4*>(out + (size_t)p * 8 + half * 4);
        *op = make_float4(a0, a1, a2, a3);
    }
}

extern "C" void kernel_launch(void* const* d_in, const int* in_sizes, int n_in,
                              void* d_out, int out_size)
{
    const float* coord    = (const float*)d_in[0];  // (N,3)
    const float* features = (const float*)d_in[1];  // (3,TABLE,8)
    const int*   indices  = (const int*)d_in[2];    // (3,N,8)
    float*       out      = (float*)d_out;          // (N,8)

    const int n = in_sizes[0] / 3;
    const int threads = 256;
    const int blocks = (n + 127) / 128;  // 128 points/block (8 warps x 16)

    octree_pass0_kernel<<<blocks, threads>>>(
        coord, features + (size_t)2 * TABLE * FEAT_DIM, indices, out, n);
    octree_pass12_kernel<<<blocks, threads>>>(
        coord, features, indices, out, n);
}